// round 5
// baseline (speedup 1.0000x reference)
#include <cuda_runtime.h>
#include <cuda_bf16.h>
#include <cstdint>

// Problem constants (fixed by the reference)
#define NNODES 50000
#define NEDGES 600000
#define DIM    128
#define OUTD   64

// Scratch: ping-pong node feature buffers (no cudaMalloc allowed)
__device__ float g_m[(size_t)NNODES * DIM];   // GEMM output  (25.6 MB)
__device__ float g_h[(size_t)NNODES * DIM];   // scatter dest (25.6 MB)
__device__ int   g_is64;                      // edge_index dtype flag

// ---------------------------------------------------------------------------
// Detect whether edge_index is int64 or int32.
// If int64 (values in [0, 50000), little-endian), every odd int32 word is 0.
// Probability of 16 random int32 indices all being 0 is ~0.
// ---------------------------------------------------------------------------
__global__ void detect_idx_width_kernel(const int* __restrict__ ei32) {
    if (threadIdx.x == 0 && blockIdx.x == 0) {
        int acc = 0;
        #pragma unroll
        for (int i = 0; i < 16; i++) acc |= ei32[2 * i + 1];
        g_is64 = (acc == 0) ? 1 : 0;
    }
}

// ---------------------------------------------------------------------------
// Vectorized global reduction (sm_90+): red.global.add.v4.f32
// ---------------------------------------------------------------------------
__device__ __forceinline__ void red_add_v4(float* p, float4 v) {
#if __CUDA_ARCH__ >= 900
    asm volatile("red.global.add.v4.f32 [%0], {%1, %2, %3, %4};"
                 :: "l"(p), "f"(v.x), "f"(v.y), "f"(v.z), "f"(v.w)
                 : "memory");
#else
    atomicAdd(p + 0, v.x);
    atomicAdd(p + 1, v.y);
    atomicAdd(p + 2, v.z);
    atomicAdd(p + 3, v.w);
#endif
}

// ---------------------------------------------------------------------------
// Scatter-add: for each edge e, h[dst[e]] += m[src[e]]  (128 floats / row).
// One warp per edge; each lane moves one float4 (512 B per warp, coalesced).
// m and h are both L2-resident (25.6 MB each).
// ---------------------------------------------------------------------------
__global__ __launch_bounds__(256)
void scatter_add_kernel(const void* __restrict__ ei_raw, int E) {
    int warp = (blockIdx.x * blockDim.x + threadIdx.x) >> 5;
    if (warp >= E) return;
    int lane = threadIdx.x & 31;

    int src, dst;
    if (g_is64) {
        const long long* ei = (const long long*)ei_raw;
        src = (int)ei[warp];
        dst = (int)ei[E + warp];
    } else {
        const int* ei = (const int*)ei_raw;
        src = ei[warp];
        dst = ei[E + warp];
    }

    const float4 v = *reinterpret_cast<const float4*>(
        g_m + (size_t)src * DIM + lane * 4);
    red_add_v4(g_h + (size_t)dst * DIM + lane * 4, v);
}

// ---------------------------------------------------------------------------
// Tiled fp32 GEMM:  C[N x BN] = op(A)[N x 128] @ W[128 x BN] + bias
//   op(A) = relu(A) if RELU_IN.
//   If ZERO_H: after a block finishes reading its 64 exclusive A rows,
//   it zeroes the corresponding rows of g_h (prepping the next scatter).
// BM=64, BK=32, TM=8, TN=4. THREADS = 8 * (BN/4).
// ---------------------------------------------------------------------------
template <int BN, bool RELU_IN, bool ZERO_H>
__global__ __launch_bounds__((64 / 8) * (BN / 4))
void gemm_kernel(const float* __restrict__ A,
                 const float* __restrict__ W,
                 const float* __restrict__ bias,
                 float* __restrict__ C,
                 float* __restrict__ H,
                 int Nrows) {
    constexpr int BM = 64;
    constexpr int BK = 32;
    constexpr int TM = 8;
    constexpr int TN = 4;
    constexpr int THREADS = (BM / TM) * (BN / TN);

    __shared__ float As[BK][BM + 4];   // transposed A tile (pad keeps 16B align: 68*4=272)
    __shared__ float Ws[BK][BN];       // W tile

    const int tid = threadIdx.x;
    const int rb  = blockIdx.x * BM;   // first row of this block

    // thread tile coordinates
    const int ty = tid / (BN / TN);    // 0..7
    const int tx = tid % (BN / TN);    // 0..BN/4-1
    const int m0 = ty * TM;
    const int n0 = tx * TN;

    float acc[TM][TN];
    #pragma unroll
    for (int i = 0; i < TM; i++)
        #pragma unroll
        for (int j = 0; j < TN; j++) acc[i][j] = 0.0f;

    for (int k0 = 0; k0 < DIM; k0 += BK) {
        // ---- load A tile (transposed into smem), optional ReLU ----
        #pragma unroll
        for (int q = tid; q < BM * (BK / 4); q += THREADS) {
            int r  = q >> 3;          // BK/4 == 8
            int c4 = q & 7;
            int row = rb + r;
            float4 v = make_float4(0.f, 0.f, 0.f, 0.f);
            if (row < Nrows)
                v = *reinterpret_cast<const float4*>(
                        A + (size_t)row * DIM + k0 + c4 * 4);
            if (RELU_IN) {
                v.x = fmaxf(v.x, 0.f); v.y = fmaxf(v.y, 0.f);
                v.z = fmaxf(v.z, 0.f); v.w = fmaxf(v.w, 0.f);
            }
            As[c4 * 4 + 0][r] = v.x;
            As[c4 * 4 + 1][r] = v.y;
            As[c4 * 4 + 2][r] = v.z;
            As[c4 * 4 + 3][r] = v.w;
        }
        // ---- load W tile ----
        #pragma unroll
        for (int q = tid; q < BK * (BN / 4); q += THREADS) {
            int kk = q / (BN / 4);
            int n4 = q % (BN / 4);
            float4 v = *reinterpret_cast<const float4*>(
                W + (size_t)(k0 + kk) * BN + n4 * 4);
            *reinterpret_cast<float4*>(&Ws[kk][n4 * 4]) = v;
        }
        __syncthreads();

        // ---- compute ----
        #pragma unroll
        for (int kk = 0; kk < BK; kk++) {
            float4 a0 = *reinterpret_cast<const float4*>(&As[kk][m0]);
            float4 a1 = *reinterpret_cast<const float4*>(&As[kk][m0 + 4]);
            float4 w  = *reinterpret_cast<const float4*>(&Ws[kk][n0]);
            float av[TM] = {a0.x, a0.y, a0.z, a0.w, a1.x, a1.y, a1.z, a1.w};
            float wv[TN] = {w.x, w.y, w.z, w.w};
            #pragma unroll
            for (int i = 0; i < TM; i++)
                #pragma unroll
                for (int j = 0; j < TN; j++)
                    acc[i][j] = fmaf(av[i], wv[j], acc[i][j]);
        }
        __syncthreads();
    }

    // ---- epilogue: bias add, store C, optionally zero g_h rows ----
    const float4 bb = *reinterpret_cast<const float4*>(bias + n0);
    #pragma unroll
    for (int i = 0; i < TM; i++) {
        int row = rb + m0 + i;
        if (row < Nrows) {
            float4 o;
            o.x = acc[i][0] + bb.x;
            o.y = acc[i][1] + bb.y;
            o.z = acc[i][2] + bb.z;
            o.w = acc[i][3] + bb.w;
            *reinterpret_cast<float4*>(C + (size_t)row * BN + n0) = o;
            if (ZERO_H) {
                *reinterpret_cast<float4*>(H + (size_t)row * DIM + n0) =
                    make_float4(0.f, 0.f, 0.f, 0.f);
            }
        }
    }
}

// ---------------------------------------------------------------------------
// Launch sequence:
//   m = x @ W1 + b1         (zero h)
//   h = scatter(m)
//   m = h @ W1 + b1         (zero h after reading)
//   h = scatter(m)
//   m = relu(h) @ W2 + b2   (zero h after reading)
//   h = scatter(m)
//   m = h @ W2 + b2         (zero h after reading)
//   h = scatter(m)
//   out = relu(h) @ Wout + bout
// ---------------------------------------------------------------------------
extern "C" void kernel_launch(void* const* d_in, const int* in_sizes, int n_in,
                              void* d_out, int out_size) {
    const float* x    = (const float*)d_in[0];
    const void*  ei   = (const void*)d_in[1];
    const float* W1   = (const float*)d_in[2];
    const float* b1   = (const float*)d_in[3];
    const float* W2   = (const float*)d_in[4];
    const float* b2   = (const float*)d_in[5];
    const float* Wout = (const float*)d_in[6];
    const float* bout = (const float*)d_in[7];
    float* out = (float*)d_out;

    float *m_ptr = nullptr, *h_ptr = nullptr;
    cudaGetSymbolAddress((void**)&m_ptr, g_m);
    cudaGetSymbolAddress((void**)&h_ptr, g_h);

    const int N = NNODES;
    const int E = NEDGES;

    const int gemm_blocks = (N + 63) / 64;             // 782
    const int scat_blocks = (E + 7) / 8;               // 8 warps (edges) per 256-thr block

    detect_idx_width_kernel<<<1, 32>>>((const int*)ei);

    // pool layer 1 (W1), iteration 1
    gemm_kernel<128, false, true><<<gemm_blocks, 256>>>(x, W1, b1, m_ptr, h_ptr, N);
    scatter_add_kernel<<<scat_blocks, 256>>>(ei, E);
    // pool layer 1 (W1), iteration 2
    gemm_kernel<128, false, true><<<gemm_blocks, 256>>>(h_ptr, W1, b1, m_ptr, h_ptr, N);
    scatter_add_kernel<<<scat_blocks, 256>>>(ei, E);
    // relu + pool layer 2 (W2), iteration 1
    gemm_kernel<128, true, true><<<gemm_blocks, 256>>>(h_ptr, W2, b2, m_ptr, h_ptr, N);
    scatter_add_kernel<<<scat_blocks, 256>>>(ei, E);
    // pool layer 2 (W2), iteration 2
    gemm_kernel<128, false, true><<<gemm_blocks, 256>>>(h_ptr, W2, b2, m_ptr, h_ptr, N);
    scatter_add_kernel<<<scat_blocks, 256>>>(ei, E);
    // relu + output projection
    gemm_kernel<64, true, false><<<gemm_blocks, 128>>>(h_ptr, Wout, bout, out, nullptr, N);
}